// round 2
// baseline (speedup 1.0000x reference)
#include <cuda_runtime.h>
#include <cuda_bf16.h>
#include <math.h>

#define EPSF 1e-5f

// ---------------- scratch (static device globals; no runtime alloc) --------
__device__ float g_big[67108864];          // up to (32,512,4096)
__device__ float g_patt[33554432];         // x_att (32,256,4096)
__device__ float g_tmp[8388608];           // (32,64,4096) reused
__device__ float g_xm[32*64*484];
__device__ float g_gsum[32*64*484];
__device__ float g_x4p[32*64*1024];
__device__ unsigned char g_idx1[32*64*1024];
__device__ float g_xp[32*64*256];
__device__ unsigned char g_idx2[32*64*256];
__device__ float g_hb[32*64*256];
__device__ float g_a1b[32*64*256];
__device__ float g_a2b[32*64*256];
__device__ float g_a1s[32*32*256];
__device__ float g_a2s[32*32*256];
__device__ float g_aggb[32*2*256];
__device__ float g_sigb[32*2*256];
__device__ float g_attnb[32*64*256];
__device__ float g_gaout[32*64*1024];
__device__ float g_mean[1024];
__device__ float g_istd[1024];

__device__ __forceinline__ float sigmoidf_(float v){ return 1.0f/(1.0f+expf(-v)); }

// ---------------- GEMM functors ---------------------------------------------
struct BLoadChan {
  const float* x; int C; int c0;
  __device__ __forceinline__ float operator()(int k,int n) const {
    int b=n>>12, p=n&4095;
    return x[((size_t)(b*C + c0 + k)<<12) + p];
  }
};
struct BLoadBNRelu {
  const float* t; int C; const float* mean; const float* istd;
  __device__ __forceinline__ float operator()(int k,int n) const {
    int b=n>>12, p=n&4095;
    float v=t[((size_t)(b*C + k)<<12)+p];
    v=(v-mean[k])*istd[k];
    return v>0.f?v:0.f;
  }
};
struct BLoadIm2col3 {
  const float* x; int C; int c0;
  __device__ __forceinline__ float operator()(int k,int n) const {
    int ic=k/9; int t=k-ic*9; int dy=t/3-1, dx=t%3-1;
    int b=n>>12, p=n&4095;
    int h=(p>>6)+dy, w=(p&63)+dx;
    if((unsigned)h>63u||(unsigned)w>63u) return 0.f;
    return x[((size_t)(b*C + c0 + ic)<<12) + h*64 + w];
  }
};
struct EpStore {
  float* o; int MC; int oc0;
  __device__ __forceinline__ void operator()(int m,int n,float a) const {
    int b=n>>12,p=n&4095;
    o[((size_t)(b*MC + oc0 + m)<<12)+p]=a;
  }
};
struct EpGateMul {               // patt ch m = x ch m * sigmoid(acc)
  float* o; const float* x;
  __device__ __forceinline__ void operator()(int m,int n,float a) const {
    int b=n>>12,p=n&4095;
    size_t xi=((size_t)(b*256 + m)<<12)+p;
    o[xi]=x[xi]*sigmoidf_(a);
  }
};
struct EpResidual {
  float* o; const float* x;
  __device__ __forceinline__ void operator()(int m,int n,float a) const {
    int b=n>>12,p=n&4095;
    size_t i=((size_t)(b*256 + m)<<12)+p;
    o[i]=x[i]+a;
  }
};

// ---------------- register-tiled SGEMM --------------------------------------
template<int BM,int BN,int BK,int TM,int TN,class BL,class EP>
__global__ __launch_bounds__((BM/TM)*(BN/TN))
void gemm_k(const float* __restrict__ A, int K, BL bl, EP ep){
  constexpr int TX=BN/TN, TY=BM/TM, NT=TX*TY;
  __shared__ __align__(16) float As[BK][BM];
  __shared__ __align__(16) float Bs[BK][BN];
  const int tid=threadIdx.x;
  const int tx=tid%TX, ty=tid/TX;
  const int m0=blockIdx.y*BM, n0=blockIdx.x*BN;
  float acc[TM][TN];
#pragma unroll
  for(int i=0;i<TM;i++)
#pragma unroll
    for(int j=0;j<TN;j++) acc[i][j]=0.f;

  for(int k0=0;k0<K;k0+=BK){
    constexpr int AIT=(BM*BK)/NT;
#pragma unroll
    for(int it=0;it<AIT;it++){
      int i=it*NT+tid; int m=i/BK, k=i%BK;
      As[k][m]=A[(size_t)(m0+m)*K + k0 + k];
    }
    constexpr int BIT=(BK*BN)/NT;
#pragma unroll
    for(int it=0;it<BIT;it++){
      int i=it*NT+tid; int k=i/BN, n=i%BN;
      Bs[k][n]=bl(k0+k, n0+n);
    }
    __syncthreads();
#pragma unroll
    for(int k=0;k<BK;k++){
      float ar[TM], br[TN];
#pragma unroll
      for(int i=0;i<TM;i+=4){
        float4 v=*reinterpret_cast<const float4*>(&As[k][ty*TM+i]);
        ar[i]=v.x;ar[i+1]=v.y;ar[i+2]=v.z;ar[i+3]=v.w;
      }
#pragma unroll
      for(int j=0;j<TN;j+=4){
        float4 v=*reinterpret_cast<const float4*>(&Bs[k][tx*TN+j]);
        br[j]=v.x;br[j+1]=v.y;br[j+2]=v.z;br[j+3]=v.w;
      }
#pragma unroll
      for(int i=0;i<TM;i++)
#pragma unroll
        for(int j=0;j<TN;j++) acc[i][j]+=ar[i]*br[j];
    }
    __syncthreads();
  }
#pragma unroll
  for(int i=0;i<TM;i++)
#pragma unroll
    for(int j=0;j<TN;j++) ep(m0+ty*TM+i, n0+tx*TN+j, acc[i][j]);
}

// ---------------- BatchNorm stats -------------------------------------------
__global__ void bn_stats_k(const float* __restrict__ d, int C, int S,
                           float* __restrict__ mean, float* __restrict__ istd){
  int c=blockIdx.x;
  int N=32*S;
  double s=0.0,s2=0.0;
  for(int e=threadIdx.x;e<N;e+=blockDim.x){
    int b=e/S, off=e-b*S;
    float v=d[(size_t)(b*C+c)*S+off];
    s+=(double)v; s2+=(double)v*(double)v;
  }
  __shared__ double sh[256], sh2[256];
  sh[threadIdx.x]=s; sh2[threadIdx.x]=s2; __syncthreads();
  for(int o=128;o>0;o>>=1){
    if(threadIdx.x<o){ sh[threadIdx.x]+=sh[threadIdx.x+o]; sh2[threadIdx.x]+=sh2[threadIdx.x+o]; }
    __syncthreads();
  }
  if(threadIdx.x==0){
    double m=sh[0]/(double)N;
    double v=sh2[0]/(double)N - m*m;
    mean[c]=(float)m; istd[c]=rsqrtf((float)v+EPSF);
  }
}

// ---------------- LA apply ---------------------------------------------------
__global__ void la_apply_k(const float* __restrict__ t, float* __restrict__ patt,
                           const float* __restrict__ mean, const float* __restrict__ istd){
  int i=blockIdx.x*blockDim.x+threadIdx.x;
  if(i>=32*64*4096) return;
  int p=i&4095; int bc=i>>12; int c=bc&63; int b=bc>>6;
  float v=(t[i]-mean[c])*istd[c];
  patt[((size_t)(b*256+64+c)<<12)+p]=v>0.f?v:0.f;
}

// ---------------- MRA --------------------------------------------------------
__global__ void mra_pool_k(const float* __restrict__ x, float* __restrict__ mp){
  int i=blockIdx.x*blockDim.x+threadIdx.x;
  if(i>=32*64*4096) return;
  int p=i&4095, bc=i>>12, c=bc&63, b=bc>>6;
  int h=p>>6, w=p&63;
  const float* X=x+(((size_t)(b*256+128+c))<<12);
  float m=-3.4e38f;
  for(int dy=-1;dy<=1;dy++){
    int y=h+dy; if((unsigned)y>63u) continue;
    for(int dx=-1;dx<=1;dx++){
      int ww=w+dx; if((unsigned)ww>63u) continue;
      float v=X[y*64+ww]; m=v>m?v:m;
    }
  }
  mp[i]=m;
}

__global__ void blur_k(const float* __restrict__ mp, float* __restrict__ xm){
  int i=blockIdx.x*blockDim.x+threadIdx.x;
  if(i>=32*64*484) return;
  int s=i%484; int bc=i/484;
  int oh=s/22, ow=s%22;
  const float* X=mp+((size_t)bc<<12);
  const float f0[4]={1.f,3.f,3.f,1.f};
  float acc=0.f;
  for(int iy=0;iy<4;iy++){
    int u=3*oh+iy-1; u=u<0?-u:u; u=u>63?126-u:u;
    float fy=f0[iy];
    for(int ix=0;ix<4;ix++){
      int v=3*ow+ix-1; v=v<0?-v:v; v=v>63?126-v:v;
      acc+=fy*f0[ix]*X[u*64+v];
    }
  }
  xm[i]=acc*(1.f/64.f);
}

__global__ void mra_strips_k(const float* __restrict__ wh1, const float* __restrict__ wv1,
                             const float* __restrict__ wh2, const float* __restrict__ wv2,
                             const float* __restrict__ xm, float* __restrict__ gsum){
  int i=blockIdx.x*blockDim.x+threadIdx.x;
  if(i>=32*64*484) return;
  int s=i%484; int bc=i/484; int c=bc&63;
  int r=s/22, cc=s%22;
  const float* X=xm+(size_t)bc*484;
  const float* W1=wh1+c*33;
  const float* V1=wv1+c*33;
  const float* W2=wh2+c*33;
  const float* V2=wv2+c*33;
  float acc=0.f;
  // xh1: (11,3) pad (5,1)
  for(int ky=0;ky<11;ky++){
    int y=r+ky-5; if((unsigned)y>=22u) continue;
    for(int kx=0;kx<3;kx++){
      int x2=cc+kx-1; if((unsigned)x2>=22u) continue;
      acc+=W1[ky*3+kx]*X[y*22+x2];
    }
  }
  // xw1: (3,11) pad (1,5)
  for(int ky=0;ky<3;ky++){
    int y=r+ky-1; if((unsigned)y>=22u) continue;
    for(int kx=0;kx<11;kx++){
      int x2=cc+kx-5; if((unsigned)x2>=22u) continue;
      acc+=V1[ky*11+kx]*X[y*22+x2];
    }
  }
  // xh2 = inv_h_tf(conv(h_tf(xm), (11,3), pad (5,1)))
  {
    int i2=r*44+cc; int R=i2/43, C=i2-43*R;
    for(int ky=0;ky<11;ky++){
      int RR=R+ky-5; if((unsigned)RR>=22u) continue;
      for(int kx=0;kx<3;kx++){
        int CC=C+kx-1; if((unsigned)CC>=43u) continue;
        int j=RR*43+CC; int q=j/44, m=j-44*q;
        if(m<22) acc+=W2[ky*3+kx]*X[q*22+m];
      }
    }
  }
  // xw2 = inv_v_tf(conv(v_tf(xm), (3,11), pad (1,5)))
  {
    int j=cc*44+r; int b2=j/43, a2=j-43*b2;   // conv output at (row=a2, col=b2) of (43,22)
    for(int ky=0;ky<3;ky++){
      int RR=a2+ky-1; if((unsigned)RR>=43u) continue;
      for(int kx=0;kx<11;kx++){
        int CC=b2+kx-5; if((unsigned)CC>=22u) continue;
        int j2=CC*43+RR; int q=j2/44, m=j2-44*q;
        if(m<22) acc+=V2[ky*11+kx]*X[m*22+q];
      }
    }
  }
  gsum[i]=acc;
}

__global__ void mra_apply_k(const float* __restrict__ x, const float* __restrict__ gsum,
                            float* __restrict__ patt,
                            const float* __restrict__ mean, const float* __restrict__ istd){
  int i=blockIdx.x*blockDim.x+threadIdx.x;
  if(i>=32*64*4096) return;
  int p=i&4095, bc=i>>12, c=bc&63, b=bc>>6;
  int h=p>>6, w=p&63;
  int ri=(h*22)>>6, ci=(w*22)>>6;
  float g=gsum[(size_t)bc*484 + ri*22+ci];
  g=sigmoidf_((g-mean[c])*istd[c]);
  size_t xi=((size_t)(b*256+128+c)<<12)+p;
  patt[xi]=x[xi]*g;
}

// ---------------- maxpool2x2 w/ argmax (first-max wins) ----------------------
__global__ void pool2_k(const float* __restrict__ in, long bstride, int c0, int inW,
                        float* __restrict__ out, unsigned char* __restrict__ idx, int total){
  int i=blockIdx.x*blockDim.x+threadIdx.x;
  if(i>=total) return;
  int outW=inW>>1; int os=outW*outW;
  int s=i%os; int bc=i/os; int b=bc>>6, c=bc&63;
  int oh=s/outW, ow=s-oh*outW;
  const float* P=in + (size_t)b*bstride + (size_t)(c0+c)*inW*inW;
  float v0=P[(2*oh)*inW+2*ow],   v1=P[(2*oh)*inW+2*ow+1];
  float v2=P[(2*oh+1)*inW+2*ow], v3=P[(2*oh+1)*inW+2*ow+1];
  float best=v0; int bi=0;
  if(v1>best){best=v1;bi=1;}
  if(v2>best){best=v2;bi=2;}
  if(v3>best){best=v3;bi=3;}
  out[i]=best; idx[i]=(unsigned char)bi;
}

// ---------------- GA kernels (16x16) -----------------------------------------
__global__ void ga_proj1_k(const float* __restrict__ xp, const float* __restrict__ w,
                           const float* __restrict__ bias, float* __restrict__ hb){
  int i=blockIdx.x*blockDim.x+threadIdx.x;
  if(i>=32*64*256) return;
  int s=i&255; int boc=i>>8; int oc=boc&63; int b=boc>>6;
  const float* X=xp+(size_t)b*64*256;
  float acc=bias[oc];
  for(int ic=0;ic<64;ic++) acc+=w[oc*64+ic]*X[ic*256+s];
  hb[i]=acc>0.f?acc:0.f;
}

__global__ void ga_dw5_k(const float* __restrict__ hb, const float* __restrict__ w,
                         const float* __restrict__ bias, float* __restrict__ a1){
  int i=blockIdx.x*blockDim.x+threadIdx.x;
  if(i>=32*64*256) return;
  int s=i&255; int bc=i>>8; int c=bc&63;
  int y=s>>4, x=s&15;
  const float* H=hb+(size_t)bc*256;
  float acc=bias[c];
  for(int ky=0;ky<5;ky++){
    int yy=y+ky-2; if((unsigned)yy>15u) continue;
    for(int kx=0;kx<5;kx++){
      int xx=x+kx-2; if((unsigned)xx>15u) continue;
      acc+=w[c*25+ky*5+kx]*H[yy*16+xx];
    }
  }
  a1[i]=acc;
}

__global__ void ga_dw7d3_k(const float* __restrict__ a1, const float* __restrict__ w,
                           const float* __restrict__ bias, float* __restrict__ a2){
  int i=blockIdx.x*blockDim.x+threadIdx.x;
  if(i>=32*64*256) return;
  int s=i&255; int bc=i>>8; int c=bc&63;
  int y=s>>4, x=s&15;
  const float* A=a1+(size_t)bc*256;
  float acc=bias[c];
  for(int ky=0;ky<7;ky++){
    int yy=y+3*ky-9; if((unsigned)yy>15u) continue;
    for(int kx=0;kx<7;kx++){
      int xx=x+3*kx-9; if((unsigned)xx>15u) continue;
      acc+=w[c*49+ky*7+kx]*A[yy*16+xx];
    }
  }
  a2[i]=acc;
}

__global__ void ga_c1c2_k(const float* __restrict__ a1, const float* __restrict__ a2,
                          const float* __restrict__ c1w, const float* __restrict__ c1b,
                          const float* __restrict__ c2w, const float* __restrict__ c2b,
                          float* __restrict__ a1s, float* __restrict__ a2s){
  int i=blockIdx.x*blockDim.x+threadIdx.x;
  if(i>=2*32*32*256) return;
  int which=i/(32*32*256); int rr=i-which*(32*32*256);
  int s=rr&255; int bj=rr>>8; int j=bj&31; int b=bj>>5;
  const float* src=which?a2:a1;
  const float* W=which?c2w:c1w;
  const float* Bb=which?c2b:c1b;
  const float* S=src+(size_t)b*64*256;
  float acc=Bb[j];
  for(int ic=0;ic<64;ic++) acc+=W[j*64+ic]*S[ic*256+s];
  (which?a2s:a1s)[(size_t)(b*32+j)*256+s]=acc;
}

__global__ void ga_agg_k(const float* __restrict__ a1s, const float* __restrict__ a2s,
                         float* __restrict__ agg){
  int i=blockIdx.x*blockDim.x+threadIdx.x;
  if(i>=32*256) return;
  int b=i>>8, s=i&255;
  const float* A1=a1s+(size_t)b*32*256;
  const float* A2=a2s+(size_t)b*32*256;
  float sum=0.f, mx=-3.4e38f;
  for(int j=0;j<32;j++){
    float v1=A1[j*256+s]; sum+=v1; mx=v1>mx?v1:mx;
    float v2=A2[j*256+s]; sum+=v2; mx=v2>mx?v2:mx;
  }
  agg[(size_t)(b*2+0)*256+s]=sum*(1.f/64.f);
  agg[(size_t)(b*2+1)*256+s]=mx;
}

__global__ void ga_sq_k(const float* __restrict__ agg, const float* __restrict__ w,
                        const float* __restrict__ bias, float* __restrict__ sg){
  int i=blockIdx.x*blockDim.x+threadIdx.x;
  if(i>=32*2*256) return;
  int s=i&255; int bo=i>>8; int o=bo&1; int b=bo>>1;
  int y=s>>4, x=s&15;
  float acc=bias[o];
  for(int ic=0;ic<2;ic++){
    const float* A=agg+(size_t)(b*2+ic)*256;
    const float* W=w+((o*2+ic)*49);
    for(int ky=0;ky<7;ky++){
      int yy=y+ky-3; if((unsigned)yy>15u) continue;
      for(int kx=0;kx<7;kx++){
        int xx=x+kx-3; if((unsigned)xx>15u) continue;
        acc+=W[ky*7+kx]*A[yy*16+xx];
      }
    }
  }
  sg[i]=sigmoidf_(acc);
}

__global__ void ga_attn_k(const float* __restrict__ a1s, const float* __restrict__ a2s,
                          const float* __restrict__ sg, const float* __restrict__ cw,
                          const float* __restrict__ cb, float* __restrict__ attn){
  int i=blockIdx.x*blockDim.x+threadIdx.x;
  if(i>=32*64*256) return;
  int s=i&255; int boc=i>>8; int oc=boc&63; int b=boc>>6;
  float s0=sg[(size_t)(b*2+0)*256+s];
  float s1=sg[(size_t)(b*2+1)*256+s];
  const float* A1=a1s+(size_t)b*32*256;
  const float* A2=a2s+(size_t)b*32*256;
  float acc=cb[oc];
  for(int j=0;j<32;j++)
    acc+=cw[oc*32+j]*(A1[j*256+s]*s0 + A2[j*256+s]*s1);
  attn[i]=acc;
}

__global__ void ga_proj2_unpool_k(const float* __restrict__ hb, const float* __restrict__ attn,
                                  const float* __restrict__ w, const float* __restrict__ bias,
                                  const unsigned char* __restrict__ idx2, float* __restrict__ out){
  int i=blockIdx.x*blockDim.x+threadIdx.x;
  if(i>=32*64*256) return;
  int s=i&255; int boc=i>>8; int oc=boc&63; int b=boc>>6;
  const float* H=hb+(size_t)b*64*256;
  const float* A=attn+(size_t)b*64*256;
  float acc=bias[oc];
  for(int ic=0;ic<64;ic++) acc+=w[oc*64+ic]*H[ic*256+s]*A[ic*256+s];
  int id=idx2[i];
  int y=s>>4, x=s&15;
  float* O=out+(size_t)boc*1024;
  for(int dy=0;dy<2;dy++)
    for(int dx=0;dx<2;dx++)
      O[(2*y+dy)*32 + 2*x+dx] = (dy*2+dx==id)?acc:0.f;
}

__global__ void ga_final_k(const float* __restrict__ gaout, const unsigned char* __restrict__ idx1,
                           float* __restrict__ patt,
                           const float* __restrict__ mean, const float* __restrict__ istd){
  int i=blockIdx.x*blockDim.x+threadIdx.x;
  if(i>=32*64*1024) return;
  int s=i&1023; int bc=i>>10; int c=bc&63; int b=bc>>6;
  float v=(gaout[i]-mean[c])*istd[c];
  int id=idx1[i];
  int y=s>>5, x=s&31;
  float* O=patt+(((size_t)(b*256+192+c))<<12);
  for(int dy=0;dy<2;dy++)
    for(int dx=0;dx<2;dx++)
      O[(2*y+dy)*64 + 2*x+dx] = (dy*2+dx==id)?v:0.f;
}

// ---------------- launch ------------------------------------------------------
extern "C" void kernel_launch(void* const* d_in, const int* in_sizes, int n_in,
                              void* d_out, int out_size) {
  const float* x      =(const float*)d_in[0];
  const float* pa_w1  =(const float*)d_in[1];
  const float* pa_w2  =(const float*)d_in[2];
  const float* la_w   =(const float*)d_in[3];
  const float* mra_h1 =(const float*)d_in[4];
  const float* mra_v1 =(const float*)d_in[5];
  const float* mra_h2 =(const float*)d_in[6];
  const float* mra_v2 =(const float*)d_in[7];
  const float* p1w=(const float*)d_in[8];  const float* p1b=(const float*)d_in[9];
  const float* c0w=(const float*)d_in[10]; const float* c0b=(const float*)d_in[11];
  const float* spw=(const float*)d_in[12]; const float* spb=(const float*)d_in[13];
  const float* c1w=(const float*)d_in[14]; const float* c1b=(const float*)d_in[15];
  const float* c2w=(const float*)d_in[16]; const float* c2b=(const float*)d_in[17];
  const float* cw =(const float*)d_in[18]; const float* cb =(const float*)d_in[19];
  const float* sqw=(const float*)d_in[20]; const float* sqb=(const float*)d_in[21];
  const float* p2w=(const float*)d_in[22]; const float* p2b=(const float*)d_in[23];
  const float* mlp_w1=(const float*)d_in[24];
  const float* mlp_w2=(const float*)d_in[25];
  float* out=(float*)d_out;

  float *big,*patt,*tmp,*xm,*gsum,*x4p,*xp,*hb,*a1b,*a2b,*a1s,*a2s,*aggb,*sigb,*attnb,*gaout,*mean,*istd;
  unsigned char *idx1,*idx2;
  cudaGetSymbolAddress((void**)&big,  g_big);
  cudaGetSymbolAddress((void**)&patt, g_patt);
  cudaGetSymbolAddress((void**)&tmp,  g_tmp);
  cudaGetSymbolAddress((void**)&xm,   g_xm);
  cudaGetSymbolAddress((void**)&gsum, g_gsum);
  cudaGetSymbolAddress((void**)&x4p,  g_x4p);
  cudaGetSymbolAddress((void**)&xp,   g_xp);
  cudaGetSymbolAddress((void**)&hb,   g_hb);
  cudaGetSymbolAddress((void**)&a1b,  g_a1b);
  cudaGetSymbolAddress((void**)&a2b,  g_a2b);
  cudaGetSymbolAddress((void**)&a1s,  g_a1s);
  cudaGetSymbolAddress((void**)&a2s,  g_a2s);
  cudaGetSymbolAddress((void**)&aggb, g_aggb);
  cudaGetSymbolAddress((void**)&sigb, g_sigb);
  cudaGetSymbolAddress((void**)&attnb,g_attnb);
  cudaGetSymbolAddress((void**)&gaout,g_gaout);
  cudaGetSymbolAddress((void**)&mean, g_mean);
  cudaGetSymbolAddress((void**)&istd, g_istd);
  cudaGetSymbolAddress((void**)&idx1, g_idx1);
  cudaGetSymbolAddress((void**)&idx2, g_idx2);

  const int T=256;

  // ---- PA ----
  gemm_k<128,128,16,8,8><<<dim3(1024,2),256>>>(pa_w1, 64, BLoadChan{x,256,0}, EpStore{big,256,0});
  bn_stats_k<<<256,T>>>(big,256,4096, mean+0, istd+0);
  gemm_k<64,128,16,4,8><<<dim3(1024,1),256>>>(pa_w2, 256, BLoadBNRelu{big,256,mean+0,istd+0}, EpGateMul{patt, x});

  // ---- LA ----
  gemm_k<64,128,16,4,8><<<dim3(1024,1),256>>>(la_w, 576, BLoadIm2col3{x,256,64}, EpStore{tmp,64,0});
  bn_stats_k<<<64,T>>>(tmp,64,4096, mean+256, istd+256);
  la_apply_k<<<32768,T>>>(tmp, patt, mean+256, istd+256);

  // ---- MRA ----
  mra_pool_k<<<32768,T>>>(x, tmp);
  blur_k<<<3872,T>>>(tmp, xm);
  mra_strips_k<<<3872,T>>>(mra_h1, mra_v1, mra_h2, mra_v2, xm, gsum);
  bn_stats_k<<<64,T>>>(gsum,64,484, mean+320, istd+320);
  mra_apply_k<<<32768,T>>>(x, gsum, patt, mean+320, istd+320);

  // ---- GA ----
  pool2_k<<<8192,T>>>(x, 256L*4096L, 192, 64, x4p, idx1, 32*64*1024);
  pool2_k<<<2048,T>>>(x4p, 64L*1024L, 0, 32, xp, idx2, 32*64*256);
  ga_proj1_k<<<2048,T>>>(xp, p1w, p1b, hb);
  ga_dw5_k<<<2048,T>>>(hb, c0w, c0b, a1b);
  ga_dw7d3_k<<<2048,T>>>(a1b, spw, spb, a2b);
  ga_c1c2_k<<<2048,T>>>(a1b, a2b, c1w, c1b, c2w, c2b, a1s, a2s);
  ga_agg_k<<<32,T>>>(a1s, a2s, aggb);
  ga_sq_k<<<64,T>>>(aggb, sqw, sqb, sigb);
  ga_attn_k<<<2048,T>>>(a1s, a2s, sigb, cw, cb, attnb);
  ga_proj2_unpool_k<<<2048,T>>>(hb, attnb, p2w, p2b, idx2, gaout);
  bn_stats_k<<<64,T>>>(gaout,64,1024, mean+384, istd+384);
  ga_final_k<<<8192,T>>>(gaout, idx1, patt, mean+384, istd+384);

  // ---- MLP ----
  gemm_k<128,128,16,8,8><<<dim3(1024,4),256>>>(mlp_w1, 256, BLoadChan{patt,256,0}, EpStore{big,512,0});
  bn_stats_k<<<512,T>>>(big,512,4096, mean+448, istd+448);
  gemm_k<128,128,16,8,8><<<dim3(1024,2),256>>>(mlp_w2, 512, BLoadBNRelu{big,512,mean+448,istd+448}, EpResidual{out, x});
}

// round 3
// speedup vs baseline: 1.1141x; 1.1141x over previous
#include <cuda_runtime.h>
#include <cuda_bf16.h>
#include <math.h>

#define EPSF 1e-5f
typedef unsigned long long u64;

// ---------------- scratch (static device globals; no runtime alloc) --------
__device__ float g_big[67108864];          // up to (32,512,4096)
__device__ float g_patt[33554432];         // x_att (32,256,4096)
__device__ float g_tmp[8388608];           // (32,64,4096) reused
__device__ float g_xm[32*64*484];
__device__ float g_gsum[32*64*484];
__device__ float g_x4p[32*64*1024];
__device__ unsigned char g_idx1[32*64*1024];
__device__ float g_xp[32*64*256];
__device__ unsigned char g_idx2[32*64*256];
__device__ float g_hb[32*64*256];
__device__ float g_a1b[32*64*256];
__device__ float g_a2b[32*64*256];
__device__ float g_a1s[32*32*256];
__device__ float g_a2s[32*32*256];
__device__ float g_aggb[32*2*256];
__device__ float g_sigb[32*2*256];
__device__ float g_attnb[32*64*256];
__device__ float g_gaout[32*64*1024];
__device__ float g_mean[1024];
__device__ float g_istd[1024];

__device__ __forceinline__ float sigmoidf_(float v){ return 1.0f/(1.0f+expf(-v)); }

// ---------------- GEMM functors ---------------------------------------------
struct BLoadChan {
  const float* x; int C; int c0;
  __device__ __forceinline__ float operator()(int k,int n) const {
    int b=n>>12, p=n&4095;
    return x[((size_t)(b*C + c0 + k)<<12) + p];
  }
};
struct BLoadBNRelu {
  const float* t; int C; const float* mean; const float* istd;
  __device__ __forceinline__ float operator()(int k,int n) const {
    int b=n>>12, p=n&4095;
    float v=t[((size_t)(b*C + k)<<12)+p];
    v=(v-mean[k])*istd[k];
    return v>0.f?v:0.f;
  }
};
struct BLoadIm2col3 {
  const float* x; int C; int c0;
  __device__ __forceinline__ float operator()(int k,int n) const {
    int ic=k/9; int t=k-ic*9; int dy=t/3-1, dx=t%3-1;
    int b=n>>12, p=n&4095;
    int h=(p>>6)+dy, w=(p&63)+dx;
    if((unsigned)h>63u||(unsigned)w>63u) return 0.f;
    return x[((size_t)(b*C + c0 + ic)<<12) + h*64 + w];
  }
};
struct EpStore {
  float* o; int MC; int oc0;
  __device__ __forceinline__ void operator()(int m,int n,float a) const {
    int b=n>>12,p=n&4095;
    o[((size_t)(b*MC + oc0 + m)<<12)+p]=a;
  }
};
struct EpGateMul {               // patt ch m = x ch m * sigmoid(acc)
  float* o; const float* x;
  __device__ __forceinline__ void operator()(int m,int n,float a) const {
    int b=n>>12,p=n&4095;
    size_t xi=((size_t)(b*256 + m)<<12)+p;
    o[xi]=x[xi]*sigmoidf_(a);
  }
};
struct EpResidual {
  float* o; const float* x;
  __device__ __forceinline__ void operator()(int m,int n,float a) const {
    int b=n>>12,p=n&4095;
    size_t i=((size_t)(b*256 + m)<<12)+p;
    o[i]=x[i]+a;
  }
};

// ---------------- register-tiled SGEMM with packed f32x2 FMA -----------------
template<int BM,int BN,int BK,int TM,int TN,class BL,class EP>
__global__ __launch_bounds__((BM/TM)*(BN/TN))
void gemm_k(const float* __restrict__ A, int K, BL bl, EP ep){
  constexpr int TX=BN/TN, TY=BM/TM, NT=TX*TY, TN2=TN/2, BMP=BM+8;
  __shared__ __align__(16) float As[BK][BMP];
  __shared__ __align__(16) float Bs[BK][BN];
  const int tid=threadIdx.x;
  const int tx=tid%TX, ty=tid/TX;
  const int m0=blockIdx.y*BM, n0=blockIdx.x*BN;
  u64 acc[TM][TN2];
#pragma unroll
  for(int i=0;i<TM;i++)
#pragma unroll
    for(int j=0;j<TN2;j++) acc[i][j]=0ull;

  for(int k0=0;k0<K;k0+=BK){
    constexpr int AIT=(BM*BK)/NT;
#pragma unroll
    for(int it=0;it<AIT;it++){
      int i=it*NT+tid; int m=i/BK, k=i%BK;
      As[k][m]=A[(size_t)(m0+m)*K + k0 + k];
    }
    constexpr int BIT=(BK*BN)/NT;
#pragma unroll
    for(int it=0;it<BIT;it++){
      int i=it*NT+tid; int k=i/BN, n=i%BN;
      Bs[k][n]=bl(k0+k, n0+n);
    }
    __syncthreads();
#pragma unroll
    for(int k=0;k<BK;k++){
      float ar[TM];
#pragma unroll
      for(int i=0;i<TM;i+=4){
        float4 v=*reinterpret_cast<const float4*>(&As[k][ty*TM+i]);
        ar[i]=v.x;ar[i+1]=v.y;ar[i+2]=v.z;ar[i+3]=v.w;
      }
      u64 a2[TM];
#pragma unroll
      for(int i=0;i<TM;i++)
        asm("mov.b64 %0, {%1, %1};" : "=l"(a2[i]) : "f"(ar[i]));
      u64 b2[TN2];
#pragma unroll
      for(int j=0;j<TN2;j+=2){
        ulonglong2 q=*reinterpret_cast<const ulonglong2*>(&Bs[k][tx*TN+2*j]);
        b2[j]=q.x; b2[j+1]=q.y;
      }
#pragma unroll
      for(int i=0;i<TM;i++)
#pragma unroll
        for(int j=0;j<TN2;j++)
          asm("fma.rn.f32x2 %0, %1, %2, %0;" : "+l"(acc[i][j]) : "l"(a2[i]), "l"(b2[j]));
    }
    __syncthreads();
  }
#pragma unroll
  for(int i=0;i<TM;i++)
#pragma unroll
    for(int j=0;j<TN2;j++){
      float lo,hi;
      asm("mov.b64 {%0, %1}, %2;" : "=f"(lo), "=f"(hi) : "l"(acc[i][j]));
      ep(m0+ty*TM+i, n0+tx*TN+2*j,   lo);
      ep(m0+ty*TM+i, n0+tx*TN+2*j+1, hi);
    }
}

// ---------------- BatchNorm stats -------------------------------------------
__global__ void bn_stats_k(const float* __restrict__ d, int C, int S,
                           float* __restrict__ mean, float* __restrict__ istd){
  int c=blockIdx.x;
  int N=32*S;
  double s=0.0,s2=0.0;
  for(int e=threadIdx.x;e<N;e+=blockDim.x){
    int b=e/S, off=e-b*S;
    float v=d[(size_t)(b*C+c)*S+off];
    s+=(double)v; s2+=(double)v*(double)v;
  }
  __shared__ double sh[256], sh2[256];
  sh[threadIdx.x]=s; sh2[threadIdx.x]=s2; __syncthreads();
  for(int o=128;o>0;o>>=1){
    if(threadIdx.x<o){ sh[threadIdx.x]+=sh[threadIdx.x+o]; sh2[threadIdx.x]+=sh2[threadIdx.x+o]; }
    __syncthreads();
  }
  if(threadIdx.x==0){
    double m=sh[0]/(double)N;
    double v=sh2[0]/(double)N - m*m;
    mean[c]=(float)m; istd[c]=rsqrtf((float)v+EPSF);
  }
}

// ---------------- LA apply ---------------------------------------------------
__global__ void la_apply_k(const float* __restrict__ t, float* __restrict__ patt,
                           const float* __restrict__ mean, const float* __restrict__ istd){
  int i=blockIdx.x*blockDim.x+threadIdx.x;
  if(i>=32*64*4096) return;
  int p=i&4095; int bc=i>>12; int c=bc&63; int b=bc>>6;
  float v=(t[i]-mean[c])*istd[c];
  patt[((size_t)(b*256+64+c)<<12)+p]=v>0.f?v:0.f;
}

// ---------------- MRA --------------------------------------------------------
__global__ void mra_pool_k(const float* __restrict__ x, float* __restrict__ mp){
  int i=blockIdx.x*blockDim.x+threadIdx.x;
  if(i>=32*64*4096) return;
  int p=i&4095, bc=i>>12, c=bc&63, b=bc>>6;
  int h=p>>6, w=p&63;
  const float* X=x+(((size_t)(b*256+128+c))<<12);
  float m=-3.4e38f;
  for(int dy=-1;dy<=1;dy++){
    int y=h+dy; if((unsigned)y>63u) continue;
    for(int dx=-1;dx<=1;dx++){
      int ww=w+dx; if((unsigned)ww>63u) continue;
      float v=X[y*64+ww]; m=v>m?v:m;
    }
  }
  mp[i]=m;
}

__global__ void blur_k(const float* __restrict__ mp, float* __restrict__ xm){
  int i=blockIdx.x*blockDim.x+threadIdx.x;
  if(i>=32*64*484) return;
  int s=i%484; int bc=i/484;
  int oh=s/22, ow=s%22;
  const float* X=mp+((size_t)bc<<12);
  const float f0[4]={1.f,3.f,3.f,1.f};
  float acc=0.f;
  for(int iy=0;iy<4;iy++){
    int u=3*oh+iy-1; u=u<0?-u:u; u=u>63?126-u:u;
    float fy=f0[iy];
    for(int ix=0;ix<4;ix++){
      int v=3*ow+ix-1; v=v<0?-v:v; v=v>63?126-v:v;
      acc+=fy*f0[ix]*X[u*64+v];
    }
  }
  xm[i]=acc*(1.f/64.f);
}

__global__ void mra_strips_k(const float* __restrict__ wh1, const float* __restrict__ wv1,
                             const float* __restrict__ wh2, const float* __restrict__ wv2,
                             const float* __restrict__ xm, float* __restrict__ gsum){
  int i=blockIdx.x*blockDim.x+threadIdx.x;
  if(i>=32*64*484) return;
  int s=i%484; int bc=i/484; int c=bc&63;
  int r=s/22, cc=s%22;
  const float* X=xm+(size_t)bc*484;
  const float* W1=wh1+c*33;
  const float* V1=wv1+c*33;
  const float* W2=wh2+c*33;
  const float* V2=wv2+c*33;
  float acc=0.f;
  // xh1: (11,3) pad (5,1)
  for(int ky=0;ky<11;ky++){
    int y=r+ky-5; if((unsigned)y>=22u) continue;
    for(int kx=0;kx<3;kx++){
      int x2=cc+kx-1; if((unsigned)x2>=22u) continue;
      acc+=W1[ky*3+kx]*X[y*22+x2];
    }
  }
  // xw1: (3,11) pad (1,5)
  for(int ky=0;ky<3;ky++){
    int y=r+ky-1; if((unsigned)y>=22u) continue;
    for(int kx=0;kx<11;kx++){
      int x2=cc+kx-5; if((unsigned)x2>=22u) continue;
      acc+=V1[ky*11+kx]*X[y*22+x2];
    }
  }
  // xh2 = inv_h_tf(conv(h_tf(xm), (11,3), pad (5,1)))
  {
    int i2=r*44+cc; int R=i2/43, C=i2-43*R;
    for(int ky=0;ky<11;ky++){
      int RR=R+ky-5; if((unsigned)RR>=22u) continue;
      for(int kx=0;kx<3;kx++){
        int CC=C+kx-1; if((unsigned)CC>=43u) continue;
        int j=RR*43+CC; int q=j/44, m=j-44*q;
        if(m<22) acc+=W2[ky*3+kx]*X[q*22+m];
      }
    }
  }
  // xw2 = inv_v_tf(conv(v_tf(xm), (3,11), pad (1,5)))
  {
    int j=cc*44+r; int b2=j/43, a2=j-43*b2;
    for(int ky=0;ky<3;ky++){
      int RR=a2+ky-1; if((unsigned)RR>=43u) continue;
      for(int kx=0;kx<11;kx++){
        int CC=b2+kx-5; if((unsigned)CC>=22u) continue;
        int j2=CC*43+RR; int q=j2/44, m=j2-44*q;
        if(m<22) acc+=V2[ky*11+kx]*X[m*22+q];
      }
    }
  }
  gsum[i]=acc;
}

__global__ void mra_apply_k(const float* __restrict__ x, const float* __restrict__ gsum,
                            float* __restrict__ patt,
                            const float* __restrict__ mean, const float* __restrict__ istd){
  int i=blockIdx.x*blockDim.x+threadIdx.x;
  if(i>=32*64*4096) return;
  int p=i&4095, bc=i>>12, c=bc&63, b=bc>>6;
  int h=p>>6, w=p&63;
  int ri=(h*22)>>6, ci=(w*22)>>6;
  float g=gsum[(size_t)bc*484 + ri*22+ci];
  g=sigmoidf_((g-mean[c])*istd[c]);
  size_t xi=((size_t)(b*256+128+c)<<12)+p;
  patt[xi]=x[xi]*g;
}

// ---------------- maxpool2x2 w/ argmax (first-max wins) ----------------------
__global__ void pool2_k(const float* __restrict__ in, long bstride, int c0, int inW,
                        float* __restrict__ out, unsigned char* __restrict__ idx, int total){
  int i=blockIdx.x*blockDim.x+threadIdx.x;
  if(i>=total) return;
  int outW=inW>>1; int os=outW*outW;
  int s=i%os; int bc=i/os; int b=bc>>6, c=bc&63;
  int oh=s/outW, ow=s-oh*outW;
  const float* P=in + (size_t)b*bstride + (size_t)(c0+c)*inW*inW;
  float v0=P[(2*oh)*inW+2*ow],   v1=P[(2*oh)*inW+2*ow+1];
  float v2=P[(2*oh+1)*inW+2*ow], v3=P[(2*oh+1)*inW+2*ow+1];
  float best=v0; int bi=0;
  if(v1>best){best=v1;bi=1;}
  if(v2>best){best=v2;bi=2;}
  if(v3>best){best=v3;bi=3;}
  out[i]=best; idx[i]=(unsigned char)bi;
}

// ---------------- GA kernels (16x16) -----------------------------------------
__global__ void ga_proj1_k(const float* __restrict__ xp, const float* __restrict__ w,
                           const float* __restrict__ bias, float* __restrict__ hb){
  int i=blockIdx.x*blockDim.x+threadIdx.x;
  if(i>=32*64*256) return;
  int s=i&255; int boc=i>>8; int oc=boc&63; int b=boc>>6;
  const float* X=xp+(size_t)b*64*256;
  float acc=bias[oc];
  for(int ic=0;ic<64;ic++) acc+=w[oc*64+ic]*X[ic*256+s];
  hb[i]=acc>0.f?acc:0.f;
}

__global__ void ga_dw5_k(const float* __restrict__ hb, const float* __restrict__ w,
                         const float* __restrict__ bias, float* __restrict__ a1){
  int i=blockIdx.x*blockDim.x+threadIdx.x;
  if(i>=32*64*256) return;
  int s=i&255; int bc=i>>8; int c=bc&63;
  int y=s>>4, x=s&15;
  const float* H=hb+(size_t)bc*256;
  float acc=bias[c];
  for(int ky=0;ky<5;ky++){
    int yy=y+ky-2; if((unsigned)yy>15u) continue;
    for(int kx=0;kx<5;kx++){
      int xx=x+kx-2; if((unsigned)xx>15u) continue;
      acc+=w[c*25+ky*5+kx]*H[yy*16+xx];
    }
  }
  a1[i]=acc;
}

__global__ void ga_dw7d3_k(const float* __restrict__ a1, const float* __restrict__ w,
                           const float* __restrict__ bias, float* __restrict__ a2){
  int i=blockIdx.x*blockDim.x+threadIdx.x;
  if(i>=32*64*256) return;
  int s=i&255; int bc=i>>8; int c=bc&63;
  int y=s>>4, x=s&15;
  const float* A=a1+(size_t)bc*256;
  float acc=bias[c];
  for(int ky=0;ky<7;ky++){
    int yy=y+3*ky-9; if((unsigned)yy>15u) continue;
    for(int kx=0;kx<7;kx++){
      int xx=x+3*kx-9; if((unsigned)xx>15u) continue;
      acc+=w[c*49+ky*7+kx]*A[yy*16+xx];
    }
  }
  a2[i]=acc;
}

__global__ void ga_c1c2_k(const float* __restrict__ a1, const float* __restrict__ a2,
                          const float* __restrict__ c1w, const float* __restrict__ c1b,
                          const float* __restrict__ c2w, const float* __restrict__ c2b,
                          float* __restrict__ a1s, float* __restrict__ a2s){
  int i=blockIdx.x*blockDim.x+threadIdx.x;
  if(i>=2*32*32*256) return;
  int which=i/(32*32*256); int rr=i-which*(32*32*256);
  int s=rr&255; int bj=rr>>8; int j=bj&31; int b=bj>>5;
  const float* src=which?a2:a1;
  const float* W=which?c2w:c1w;
  const float* Bb=which?c2b:c1b;
  const float* S=src+(size_t)b*64*256;
  float acc=Bb[j];
  for(int ic=0;ic<64;ic++) acc+=W[j*64+ic]*S[ic*256+s];
  (which?a2s:a1s)[(size_t)(b*32+j)*256+s]=acc;
}

__global__ void ga_agg_k(const float* __restrict__ a1s, const float* __restrict__ a2s,
                         float* __restrict__ agg){
  int i=blockIdx.x*blockDim.x+threadIdx.x;
  if(i>=32*256) return;
  int b=i>>8, s=i&255;
  const float* A1=a1s+(size_t)b*32*256;
  const float* A2=a2s+(size_t)b*32*256;
  float sum=0.f, mx=-3.4e38f;
  for(int j=0;j<32;j++){
    float v1=A1[j*256+s]; sum+=v1; mx=v1>mx?v1:mx;
    float v2=A2[j*256+s]; sum+=v2; mx=v2>mx?v2:mx;
  }
  agg[(size_t)(b*2+0)*256+s]=sum*(1.f/64.f);
  agg[(size_t)(b*2+1)*256+s]=mx;
}

__global__ void ga_sq_k(const float* __restrict__ agg, const float* __restrict__ w,
                        const float* __restrict__ bias, float* __restrict__ sg){
  int i=blockIdx.x*blockDim.x+threadIdx.x;
  if(i>=32*2*256) return;
  int s=i&255; int bo=i>>8; int o=bo&1; int b=bo>>1;
  int y=s>>4, x=s&15;
  float acc=bias[o];
  for(int ic=0;ic<2;ic++){
    const float* A=agg+(size_t)(b*2+ic)*256;
    const float* W=w+((o*2+ic)*49);
    for(int ky=0;ky<7;ky++){
      int yy=y+ky-3; if((unsigned)yy>15u) continue;
      for(int kx=0;kx<7;kx++){
        int xx=x+kx-3; if((unsigned)xx>15u) continue;
        acc+=W[ky*7+kx]*A[yy*16+xx];
      }
    }
  }
  sg[i]=sigmoidf_(acc);
}

__global__ void ga_attn_k(const float* __restrict__ a1s, const float* __restrict__ a2s,
                          const float* __restrict__ sg, const float* __restrict__ cw,
                          const float* __restrict__ cb, float* __restrict__ attn){
  int i=blockIdx.x*blockDim.x+threadIdx.x;
  if(i>=32*64*256) return;
  int s=i&255; int boc=i>>8; int oc=boc&63; int b=boc>>6;
  float s0=sg[(size_t)(b*2+0)*256+s];
  float s1=sg[(size_t)(b*2+1)*256+s];
  const float* A1=a1s+(size_t)b*32*256;
  const float* A2=a2s+(size_t)b*32*256;
  float acc=cb[oc];
  for(int j=0;j<32;j++)
    acc+=cw[oc*32+j]*(A1[j*256+s]*s0 + A2[j*256+s]*s1);
  attn[i]=acc;
}

__global__ void ga_proj2_unpool_k(const float* __restrict__ hb, const float* __restrict__ attn,
                                  const float* __restrict__ w, const float* __restrict__ bias,
                                  const unsigned char* __restrict__ idx2, float* __restrict__ out){
  int i=blockIdx.x*blockDim.x+threadIdx.x;
  if(i>=32*64*256) return;
  int s=i&255; int boc=i>>8; int oc=boc&63; int b=boc>>6;
  const float* H=hb+(size_t)b*64*256;
  const float* A=attn+(size_t)b*64*256;
  float acc=bias[oc];
  for(int ic=0;ic<64;ic++) acc+=w[oc*64+ic]*H[ic*256+s]*A[ic*256+s];
  int id=idx2[i];
  int y=s>>4, x=s&15;
  float* O=out+(size_t)boc*1024;
  for(int dy=0;dy<2;dy++)
    for(int dx=0;dx<2;dx++)
      O[(2*y+dy)*32 + 2*x+dx] = (dy*2+dx==id)?acc:0.f;
}

__global__ void ga_final_k(const float* __restrict__ gaout, const unsigned char* __restrict__ idx1,
                           float* __restrict__ patt,
                           const float* __restrict__ mean, const float* __restrict__ istd){
  int i=blockIdx.x*blockDim.x+threadIdx.x;
  if(i>=32*64*1024) return;
  int s=i&1023; int bc=i>>10; int c=bc&63; int b=bc>>6;
  float v=(gaout[i]-mean[c])*istd[c];
  int id=idx1[i];
  int y=s>>5, x=s&31;
  float* O=patt+(((size_t)(b*256+192+c))<<12);
  for(int dy=0;dy<2;dy++)
    for(int dx=0;dx<2;dx++)
      O[(2*y+dy)*64 + 2*x+dx] = (dy*2+dx==id)?v:0.f;
}

// ---------------- launch ------------------------------------------------------
extern "C" void kernel_launch(void* const* d_in, const int* in_sizes, int n_in,
                              void* d_out, int out_size) {
  const float* x      =(const float*)d_in[0];
  const float* pa_w1  =(const float*)d_in[1];
  const float* pa_w2  =(const float*)d_in[2];
  const float* la_w   =(const float*)d_in[3];
  const float* mra_h1 =(const float*)d_in[4];
  const float* mra_v1 =(const float*)d_in[5];
  const float* mra_h2 =(const float*)d_in[6];
  const float* mra_v2 =(const float*)d_in[7];
  const float* p1w=(const float*)d_in[8];  const float* p1b=(const float*)d_in[9];
  const float* c0w=(const float*)d_in[10]; const float* c0b=(const float*)d_in[11];
  const float* spw=(const float*)d_in[12]; const float* spb=(const float*)d_in[13];
  const float* c1w=(const float*)d_in[14]; const float* c1b=(const float*)d_in[15];
  const float* c2w=(const float*)d_in[16]; const float* c2b=(const float*)d_in[17];
  const float* cw =(const float*)d_in[18]; const float* cb =(const float*)d_in[19];
  const float* sqw=(const float*)d_in[20]; const float* sqb=(const float*)d_in[21];
  const float* p2w=(const float*)d_in[22]; const float* p2b=(const float*)d_in[23];
  const float* mlp_w1=(const float*)d_in[24];
  const float* mlp_w2=(const float*)d_in[25];
  float* out=(float*)d_out;

  float *big,*patt,*tmp,*xm,*gsum,*x4p,*xp,*hb,*a1b,*a2b,*a1s,*a2s,*aggb,*sigb,*attnb,*gaout,*mean,*istd;
  unsigned char *idx1,*idx2;
  cudaGetSymbolAddress((void**)&big,  g_big);
  cudaGetSymbolAddress((void**)&patt, g_patt);
  cudaGetSymbolAddress((void**)&tmp,  g_tmp);
  cudaGetSymbolAddress((void**)&xm,   g_xm);
  cudaGetSymbolAddress((void**)&gsum, g_gsum);
  cudaGetSymbolAddress((void**)&x4p,  g_x4p);
  cudaGetSymbolAddress((void**)&xp,   g_xp);
  cudaGetSymbolAddress((void**)&hb,   g_hb);
  cudaGetSymbolAddress((void**)&a1b,  g_a1b);
  cudaGetSymbolAddress((void**)&a2b,  g_a2b);
  cudaGetSymbolAddress((void**)&a1s,  g_a1s);
  cudaGetSymbolAddress((void**)&a2s,  g_a2s);
  cudaGetSymbolAddress((void**)&aggb, g_aggb);
  cudaGetSymbolAddress((void**)&sigb, g_sigb);
  cudaGetSymbolAddress((void**)&attnb,g_attnb);
  cudaGetSymbolAddress((void**)&gaout,g_gaout);
  cudaGetSymbolAddress((void**)&mean, g_mean);
  cudaGetSymbolAddress((void**)&istd, g_istd);
  cudaGetSymbolAddress((void**)&idx1, g_idx1);
  cudaGetSymbolAddress((void**)&idx2, g_idx2);

  const int T=256;

  // ---- PA ----
  gemm_k<128,128,16,8,8><<<dim3(1024,2),256>>>(pa_w1, 64, BLoadChan{x,256,0}, EpStore{big,256,0});
  bn_stats_k<<<256,T>>>(big,256,4096, mean+0, istd+0);
  gemm_k<64,256,16,8,8><<<dim3(512,1),256>>>(pa_w2, 256, BLoadBNRelu{big,256,mean+0,istd+0}, EpGateMul{patt, x});

  // ---- LA ----
  gemm_k<64,256,16,8,8><<<dim3(512,1),256>>>(la_w, 576, BLoadIm2col3{x,256,64}, EpStore{tmp,64,0});
  bn_stats_k<<<64,T>>>(tmp,64,4096, mean+256, istd+256);
  la_apply_k<<<32768,T>>>(tmp, patt, mean+256, istd+256);

  // ---- MRA ----
  mra_pool_k<<<32768,T>>>(x, tmp);
  blur_k<<<3872,T>>>(tmp, xm);
  mra_strips_k<<<3872,T>>>(mra_h1, mra_v1, mra_h2, mra_v2, xm, gsum);
  bn_stats_k<<<64,T>>>(gsum,64,484, mean+320, istd+320);
  mra_apply_k<<<32768,T>>>(x, gsum, patt, mean+320, istd+320);

  // ---- GA ----
  pool2_k<<<8192,T>>>(x, 256L*4096L, 192, 64, x4p, idx1, 32*64*1024);
  pool2_k<<<2048,T>>>(x4p, 64L*1024L, 0, 32, xp, idx2, 32*64*256);
  ga_proj1_k<<<2048,T>>>(xp, p1w, p1b, hb);
  ga_dw5_k<<<2048,T>>>(hb, c0w, c0b, a1b);
  ga_dw7d3_k<<<2048,T>>>(a1b, spw, spb, a2b);
  ga_c1c2_k<<<2048,T>>>(a1b, a2b, c1w, c1b, c2w, c2b, a1s, a2s);
  ga_agg_k<<<32,T>>>(a1s, a2s, aggb);
  ga_sq_k<<<64,T>>>(aggb, sqw, sqb, sigb);
  ga_attn_k<<<2048,T>>>(a1s, a2s, sigb, cw, cb, attnb);
  ga_proj2_unpool_k<<<2048,T>>>(hb, attnb, p2w, p2b, idx2, gaout);
  bn_stats_k<<<64,T>>>(gaout,64,1024, mean+384, istd+384);
  ga_final_k<<<8192,T>>>(gaout, idx1, patt, mean+384, istd+384);

  // ---- MLP ----
  gemm_k<128,128,16,8,8><<<dim3(1024,4),256>>>(mlp_w1, 256, BLoadChan{patt,256,0}, EpStore{big,512,0});
  bn_stats_k<<<512,T>>>(big,512,4096, mean+448, istd+448);
  gemm_k<128,128,16,8,8><<<dim3(1024,2),256>>>(mlp_w2, 512, BLoadBNRelu{big,512,mean+448,istd+448}, EpResidual{out, x});
}